// round 2
// baseline (speedup 1.0000x reference)
#include <cuda_runtime.h>

// HardwareVMMoperation: out = sum_{c<32} Q(x[:,128c:128c+128] @ W[:,128c:128c+128]^T) + bias
// x: [B, K] fp32, W: [N, K] fp32, bias: [N] fp32, out: [B, N] fp32
// B=8192, K=N=4096 (B derived from in_sizes).
// Q(p) = rint(clamp(p,-2.56,2.56) * 255/2.56) * (2.56/255), round-half-even.

#define K_DIM  4096
#define N_DIM  4096
#define BM     128
#define BN     128
#define KS     16          // k per substep
#define THREADS 256
#define NSUB   (K_DIM / KS)   // 256 substeps
#define SUB_PER_CHUNK 8       // 128 / 16

__device__ __forceinline__ unsigned long long dup2(float v) {
    unsigned long long r;
    asm("mov.b64 %0, {%1, %1};" : "=l"(r) : "f"(v));
    return r;
}

__device__ __forceinline__ void ffma2(unsigned long long &d,
                                      unsigned long long a,
                                      unsigned long long b) {
    asm("fma.rn.f32x2 %0, %1, %2, %0;" : "+l"(d) : "l"(a), "l"(b));
}

__device__ __forceinline__ float2 unpack2(unsigned long long v) {
    float2 f;
    asm("mov.b64 {%0, %1}, %2;" : "=f"(f.x), "=f"(f.y) : "l"(v));
    return f;
}

__device__ __forceinline__ float quantize_partial(float p) {
    float y = fminf(fmaxf(p, -2.56f), 2.56f);
    y = y * (255.0f / 2.56f);   // 99.609375, exactly representable
    y = rintf(y);               // round half to even == jnp.round
    return y * (2.56f / 255.0f);
}

__global__ void __launch_bounds__(THREADS, 1)
vmm_quant_kernel(const float* __restrict__ x,
                 const float* __restrict__ w,
                 const float* __restrict__ bias,
                 float* __restrict__ out) {
    // k-major smem tiles (transposed on store), double buffered
    __shared__ __align__(16) float As[2][KS][BM];
    __shared__ __align__(16) float Bs[2][KS][BN];

    const int tid = threadIdx.x;
    const int tx  = tid & 15;   // n sub-tile
    const int ty  = tid >> 4;   // m sub-tile
    const int n0  = blockIdx.x * BN;
    const int m0  = blockIdx.y * BM;

    // loader mapping: 512 float4 per matrix per substep; 2 per thread
    const int ldr = tid >> 2;   // 0..63 (row), second row = ldr+64
    const int ldq = tid & 3;    // k-quad within substep (4 quads * 4 = 16 k)

    const float* ax = x + (size_t)(m0 + ldr) * K_DIM + ldq * 4;
    const float* bx = w + (size_t)(n0 + ldr) * K_DIM + ldq * 4;

    unsigned long long pacc[4][8];   // packed fp32x2 partial (rows 2mi, 2mi+1)
    float racc[8][8];                // running quantized accumulator
    #pragma unroll
    for (int i = 0; i < 4; ++i)
        #pragma unroll
        for (int j = 0; j < 8; ++j) pacc[i][j] = 0ULL;
    #pragma unroll
    for (int i = 0; i < 8; ++i)
        #pragma unroll
        for (int j = 0; j < 8; ++j) racc[i][j] = 0.0f;

    // ---- prologue: substep 0 -> buf 0 ----
    {
        float4 a0 = *(const float4*)(ax);
        float4 a1 = *(const float4*)(ax + (size_t)64 * K_DIM);
        float4 b0 = *(const float4*)(bx);
        float4 b1 = *(const float4*)(bx + (size_t)64 * K_DIM);
        As[0][ldq * 4 + 0][ldr]      = a0.x;
        As[0][ldq * 4 + 1][ldr]      = a0.y;
        As[0][ldq * 4 + 2][ldr]      = a0.z;
        As[0][ldq * 4 + 3][ldr]      = a0.w;
        As[0][ldq * 4 + 0][ldr + 64] = a1.x;
        As[0][ldq * 4 + 1][ldr + 64] = a1.y;
        As[0][ldq * 4 + 2][ldr + 64] = a1.z;
        As[0][ldq * 4 + 3][ldr + 64] = a1.w;
        Bs[0][ldq * 4 + 0][ldr]      = b0.x;
        Bs[0][ldq * 4 + 1][ldr]      = b0.y;
        Bs[0][ldq * 4 + 2][ldr]      = b0.z;
        Bs[0][ldq * 4 + 3][ldr]      = b0.w;
        Bs[0][ldq * 4 + 0][ldr + 64] = b1.x;
        Bs[0][ldq * 4 + 1][ldr + 64] = b1.y;
        Bs[0][ldq * 4 + 2][ldr + 64] = b1.z;
        Bs[0][ldq * 4 + 3][ldr + 64] = b1.w;
    }
    __syncthreads();

    int buf = 0;
    for (int s = 0; s < NSUB; ++s) {
        // prefetch next substep into registers (hidden under compute)
        float4 a0, a1, b0, b1;
        const bool has_next = (s + 1 < NSUB);
        if (has_next) {
            const float* ap = ax + (size_t)(s + 1) * KS;
            const float* bp = bx + (size_t)(s + 1) * KS;
            a0 = *(const float4*)(ap);
            a1 = *(const float4*)(ap + (size_t)64 * K_DIM);
            b0 = *(const float4*)(bp);
            b1 = *(const float4*)(bp + (size_t)64 * K_DIM);
        }

        // ---- compute 16 k-steps from smem[buf] ----
        #pragma unroll
        for (int kk = 0; kk < KS; ++kk) {
            ulonglong2 av0 = *(const ulonglong2*)&As[buf][kk][ty * 8];
            ulonglong2 av1 = *(const ulonglong2*)&As[buf][kk][ty * 8 + 4];
            float4 bv0 = *(const float4*)&Bs[buf][kk][tx * 8];
            float4 bv1 = *(const float4*)&Bs[buf][kk][tx * 8 + 4];

            unsigned long long am[4] = {av0.x, av0.y, av1.x, av1.y};
            unsigned long long bd[8] = {dup2(bv0.x), dup2(bv0.y), dup2(bv0.z), dup2(bv0.w),
                                        dup2(bv1.x), dup2(bv1.y), dup2(bv1.z), dup2(bv1.w)};
            #pragma unroll
            for (int mi = 0; mi < 4; ++mi)
                #pragma unroll
                for (int j = 0; j < 8; ++j)
                    ffma2(pacc[mi][j], am[mi], bd[j]);
        }

        // ---- per-128-K-chunk ADC quantization ----
        if ((s & (SUB_PER_CHUNK - 1)) == (SUB_PER_CHUNK - 1)) {
            #pragma unroll
            for (int mi = 0; mi < 4; ++mi)
                #pragma unroll
                for (int j = 0; j < 8; ++j) {
                    float2 p = unpack2(pacc[mi][j]);
                    racc[2 * mi + 0][j] += quantize_partial(p.x);
                    racc[2 * mi + 1][j] += quantize_partial(p.y);
                    pacc[mi][j] = 0ULL;
                }
        }

        // ---- stage next tile into the other buffer ----
        if (has_next) {
            const int nb = buf ^ 1;
            As[nb][ldq * 4 + 0][ldr]      = a0.x;
            As[nb][ldq * 4 + 1][ldr]      = a0.y;
            As[nb][ldq * 4 + 2][ldr]      = a0.z;
            As[nb][ldq * 4 + 3][ldr]      = a0.w;
            As[nb][ldq * 4 + 0][ldr + 64] = a1.x;
            As[nb][ldq * 4 + 1][ldr + 64] = a1.y;
            As[nb][ldq * 4 + 2][ldr + 64] = a1.z;
            As[nb][ldq * 4 + 3][ldr + 64] = a1.w;
            Bs[nb][ldq * 4 + 0][ldr]      = b0.x;
            Bs[nb][ldq * 4 + 1][ldr]      = b0.y;
            Bs[nb][ldq * 4 + 2][ldr]      = b0.z;
            Bs[nb][ldq * 4 + 3][ldr]      = b0.w;
            Bs[nb][ldq * 4 + 0][ldr + 64] = b1.x;
            Bs[nb][ldq * 4 + 1][ldr + 64] = b1.y;
            Bs[nb][ldq * 4 + 2][ldr + 64] = b1.z;
            Bs[nb][ldq * 4 + 3][ldr + 64] = b1.w;
            __syncthreads();
            buf = nb;
        }
    }

    // ---- epilogue: add bias, store ----
    const float* bptr = bias + n0 + tx * 8;
    float4 bb0 = *(const float4*)(bptr);
    float4 bb1 = *(const float4*)(bptr + 4);

    #pragma unroll
    for (int r = 0; r < 8; ++r) {
        float* op = out + (size_t)(m0 + ty * 8 + r) * N_DIM + n0 + tx * 8;
        float4 o0, o1;
        o0.x = racc[r][0] + bb0.x;
        o0.y = racc[r][1] + bb0.y;
        o0.z = racc[r][2] + bb0.z;
        o0.w = racc[r][3] + bb0.w;
        o1.x = racc[r][4] + bb1.x;
        o1.y = racc[r][5] + bb1.y;
        o1.z = racc[r][6] + bb1.z;
        o1.w = racc[r][7] + bb1.w;
        *(float4*)(op)     = o0;
        *(float4*)(op + 4) = o1;
    }
}

extern "C" void kernel_launch(void* const* d_in, const int* in_sizes, int n_in,
                              void* d_out, int out_size) {
    const float* x    = (const float*)d_in[0];
    const float* w    = (const float*)d_in[1];
    const float* bias = (const float*)d_in[2];
    float* out = (float*)d_out;

    const int Bdim = in_sizes[0] / K_DIM;   // 8192
    dim3 grid(N_DIM / BN, Bdim / BM);       // (32, 64)
    vmm_quant_kernel<<<grid, THREADS>>>(x, w, bias, out);
}

// round 3
// speedup vs baseline: 1.0006x; 1.0006x over previous
#include <cuda_runtime.h>

// HardwareVMMoperation: out = sum_{c<32} Q(x[:,128c:128c+128] @ W[:,128c:128c+128]^T) + bias
// x: [B, K] fp32, W: [N, K] fp32, bias: [N] fp32, out: [B, N] fp32
// B=8192, K=N=4096 (B derived from in_sizes).
// Q(p) = rint(clamp(p,-2.56,2.56) * 255/2.56) * (2.56/255), round-half-even.

#define K_DIM  4096
#define N_DIM  4096
#define BM     128
#define BN     128
#define KS     16          // k per substep
#define THREADS 256
#define NSUB   (K_DIM / KS)   // 256 substeps
#define SUB_PER_CHUNK 8       // 128 / 16

__device__ __forceinline__ unsigned long long dup2(float v) {
    unsigned long long r;
    asm("mov.b64 %0, {%1, %1};" : "=l"(r) : "f"(v));
    return r;
}

__device__ __forceinline__ void ffma2(unsigned long long &d,
                                      unsigned long long a,
                                      unsigned long long b) {
    asm("fma.rn.f32x2 %0, %1, %2, %0;" : "+l"(d) : "l"(a), "l"(b));
}

__device__ __forceinline__ float2 unpack2(unsigned long long v) {
    float2 f;
    asm("mov.b64 {%0, %1}, %2;" : "=f"(f.x), "=f"(f.y) : "l"(v));
    return f;
}

__device__ __forceinline__ float quantize_partial(float p) {
    float y = fminf(fmaxf(p, -2.56f), 2.56f);
    y = y * (255.0f / 2.56f);   // 99.609375, exactly representable
    y = rintf(y);               // round half to even == jnp.round
    return y * (2.56f / 255.0f);
}

__global__ void __launch_bounds__(THREADS, 1)
vmm_quant_kernel(const float* __restrict__ x,
                 const float* __restrict__ w,
                 const float* __restrict__ bias,
                 float* __restrict__ out) {
    // k-major smem tiles (transposed on store), double buffered
    __shared__ __align__(16) float As[2][KS][BM];
    __shared__ __align__(16) float Bs[2][KS][BN];

    const int tid = threadIdx.x;
    const int tx  = tid & 15;   // n sub-tile
    const int ty  = tid >> 4;   // m sub-tile
    const int n0  = blockIdx.x * BN;
    const int m0  = blockIdx.y * BM;

    // loader mapping: 512 float4 per matrix per substep; 2 per thread
    const int ldr = tid >> 2;   // 0..63 (row), second row = ldr+64
    const int ldq = tid & 3;    // k-quad within substep (4 quads * 4 = 16 k)

    const float* ax = x + (size_t)(m0 + ldr) * K_DIM + ldq * 4;
    const float* bx = w + (size_t)(n0 + ldr) * K_DIM + ldq * 4;

    unsigned long long pacc[4][8];   // packed fp32x2 partial (rows 2mi, 2mi+1)
    float racc[8][8];                // running quantized accumulator
    #pragma unroll
    for (int i = 0; i < 4; ++i)
        #pragma unroll
        for (int j = 0; j < 8; ++j) pacc[i][j] = 0ULL;
    #pragma unroll
    for (int i = 0; i < 8; ++i)
        #pragma unroll
        for (int j = 0; j < 8; ++j) racc[i][j] = 0.0f;

    // ---- prologue: substep 0 -> buf 0 ----
    {
        float4 a0 = *(const float4*)(ax);
        float4 a1 = *(const float4*)(ax + (size_t)64 * K_DIM);
        float4 b0 = *(const float4*)(bx);
        float4 b1 = *(const float4*)(bx + (size_t)64 * K_DIM);
        As[0][ldq * 4 + 0][ldr]      = a0.x;
        As[0][ldq * 4 + 1][ldr]      = a0.y;
        As[0][ldq * 4 + 2][ldr]      = a0.z;
        As[0][ldq * 4 + 3][ldr]      = a0.w;
        As[0][ldq * 4 + 0][ldr + 64] = a1.x;
        As[0][ldq * 4 + 1][ldr + 64] = a1.y;
        As[0][ldq * 4 + 2][ldr + 64] = a1.z;
        As[0][ldq * 4 + 3][ldr + 64] = a1.w;
        Bs[0][ldq * 4 + 0][ldr]      = b0.x;
        Bs[0][ldq * 4 + 1][ldr]      = b0.y;
        Bs[0][ldq * 4 + 2][ldr]      = b0.z;
        Bs[0][ldq * 4 + 3][ldr]      = b0.w;
        Bs[0][ldq * 4 + 0][ldr + 64] = b1.x;
        Bs[0][ldq * 4 + 1][ldr + 64] = b1.y;
        Bs[0][ldq * 4 + 2][ldr + 64] = b1.z;
        Bs[0][ldq * 4 + 3][ldr + 64] = b1.w;
    }
    __syncthreads();

    int buf = 0;
    for (int s = 0; s < NSUB; ++s) {
        // prefetch next substep into registers (hidden under compute)
        float4 a0, a1, b0, b1;
        const bool has_next = (s + 1 < NSUB);
        if (has_next) {
            const float* ap = ax + (size_t)(s + 1) * KS;
            const float* bp = bx + (size_t)(s + 1) * KS;
            a0 = *(const float4*)(ap);
            a1 = *(const float4*)(ap + (size_t)64 * K_DIM);
            b0 = *(const float4*)(bp);
            b1 = *(const float4*)(bp + (size_t)64 * K_DIM);
        }

        // ---- compute 16 k-steps from smem[buf] ----
        #pragma unroll
        for (int kk = 0; kk < KS; ++kk) {
            ulonglong2 av0 = *(const ulonglong2*)&As[buf][kk][ty * 8];
            ulonglong2 av1 = *(const ulonglong2*)&As[buf][kk][ty * 8 + 4];
            float4 bv0 = *(const float4*)&Bs[buf][kk][tx * 8];
            float4 bv1 = *(const float4*)&Bs[buf][kk][tx * 8 + 4];

            unsigned long long am[4] = {av0.x, av0.y, av1.x, av1.y};
            unsigned long long bd[8] = {dup2(bv0.x), dup2(bv0.y), dup2(bv0.z), dup2(bv0.w),
                                        dup2(bv1.x), dup2(bv1.y), dup2(bv1.z), dup2(bv1.w)};
            #pragma unroll
            for (int mi = 0; mi < 4; ++mi)
                #pragma unroll
                for (int j = 0; j < 8; ++j)
                    ffma2(pacc[mi][j], am[mi], bd[j]);
        }

        // ---- per-128-K-chunk ADC quantization ----
        if ((s & (SUB_PER_CHUNK - 1)) == (SUB_PER_CHUNK - 1)) {
            #pragma unroll
            for (int mi = 0; mi < 4; ++mi)
                #pragma unroll
                for (int j = 0; j < 8; ++j) {
                    float2 p = unpack2(pacc[mi][j]);
                    racc[2 * mi + 0][j] += quantize_partial(p.x);
                    racc[2 * mi + 1][j] += quantize_partial(p.y);
                    pacc[mi][j] = 0ULL;
                }
        }

        // ---- stage next tile into the other buffer ----
        if (has_next) {
            const int nb = buf ^ 1;
            As[nb][ldq * 4 + 0][ldr]      = a0.x;
            As[nb][ldq * 4 + 1][ldr]      = a0.y;
            As[nb][ldq * 4 + 2][ldr]      = a0.z;
            As[nb][ldq * 4 + 3][ldr]      = a0.w;
            As[nb][ldq * 4 + 0][ldr + 64] = a1.x;
            As[nb][ldq * 4 + 1][ldr + 64] = a1.y;
            As[nb][ldq * 4 + 2][ldr + 64] = a1.z;
            As[nb][ldq * 4 + 3][ldr + 64] = a1.w;
            Bs[nb][ldq * 4 + 0][ldr]      = b0.x;
            Bs[nb][ldq * 4 + 1][ldr]      = b0.y;
            Bs[nb][ldq * 4 + 2][ldr]      = b0.z;
            Bs[nb][ldq * 4 + 3][ldr]      = b0.w;
            Bs[nb][ldq * 4 + 0][ldr + 64] = b1.x;
            Bs[nb][ldq * 4 + 1][ldr + 64] = b1.y;
            Bs[nb][ldq * 4 + 2][ldr + 64] = b1.z;
            Bs[nb][ldq * 4 + 3][ldr + 64] = b1.w;
            __syncthreads();
            buf = nb;
        }
    }

    // ---- epilogue: add bias, store ----
    const float* bptr = bias + n0 + tx * 8;
    float4 bb0 = *(const float4*)(bptr);
    float4 bb1 = *(const float4*)(bptr + 4);

    #pragma unroll
    for (int r = 0; r < 8; ++r) {
        float* op = out + (size_t)(m0 + ty * 8 + r) * N_DIM + n0 + tx * 8;
        float4 o0, o1;
        o0.x = racc[r][0] + bb0.x;
        o0.y = racc[r][1] + bb0.y;
        o0.z = racc[r][2] + bb0.z;
        o0.w = racc[r][3] + bb0.w;
        o1.x = racc[r][4] + bb1.x;
        o1.y = racc[r][5] + bb1.y;
        o1.z = racc[r][6] + bb1.z;
        o1.w = racc[r][7] + bb1.w;
        *(float4*)(op)     = o0;
        *(float4*)(op + 4) = o1;
    }
}

extern "C" void kernel_launch(void* const* d_in, const int* in_sizes, int n_in,
                              void* d_out, int out_size) {
    const float* x    = (const float*)d_in[0];
    const float* w    = (const float*)d_in[1];
    const float* bias = (const float*)d_in[2];
    float* out = (float*)d_out;

    const int Bdim = in_sizes[0] / K_DIM;   // 8192
    dim3 grid(N_DIM / BN, Bdim / BM);       // (32, 64)
    vmm_quant_kernel<<<grid, THREADS>>>(x, w, bias, out);
}